// round 10
// baseline (speedup 1.0000x reference)
#include <cuda_runtime.h>
#include <cstdint>
#include <cstddef>

// Problem constants
#define B_   4
#define L_   4096
#define D_   2048
#define DF_  8192
#define KCAP 2048              // L * 0.5
#define BK   (B_ * KCAP)       // 8192 selected rows total

// ---------------------------------------------------------------------------
// Device scratch (static globals: allocation-free per harness rules)
// ---------------------------------------------------------------------------
__device__ float g_scores[B_ * L_];
__device__ float g_thr[B_];
__device__ int   g_cnt[B_];
__device__ int   g_idx[BK];
__device__ float g_xsel[(size_t)BK * D_];    //  64 MB (tf32-rounded)
__device__ float g_h   [(size_t)BK * DF_];   // 256 MB (tf32-rounded)
__device__ float g_w1t [(size_t)DF_ * D_];   //  64 MB (W1^T K-major, tf32-rounded)
__device__ float g_w2t [(size_t)D_ * DF_];   //  64 MB (W2^T K-major, tf32-rounded)

// ---------------------------------------------------------------------------
// Helpers
// ---------------------------------------------------------------------------
__device__ __forceinline__ uint32_t cvta_smem(const void* p) {
    uint32_t a;
    asm("{ .reg .u64 t; cvta.to.shared.u64 t, %1; cvt.u32.u64 %0, t; }"
        : "=r"(a) : "l"(p));
    return a;
}

__device__ __forceinline__ float to_tf32(float x) {
    uint32_t u;
    asm("cvt.rna.tf32.f32 %0, %1;" : "=r"(u) : "f"(x));
    return __uint_as_float(u);
}

__device__ __forceinline__ float gelu_tanh(float x) {
    float x3 = x * x * x;
    float t  = tanhf(0.7978845608028654f * (x + 0.044715f * x3));
    return 0.5f * x * (1.0f + t);
}

__device__ __forceinline__ void mma1688(float* d, const uint32_t* a, const uint32_t* b) {
    asm volatile(
        "mma.sync.aligned.m16n8k8.row.col.f32.tf32.tf32.f32 "
        "{%0,%1,%2,%3}, {%4,%5,%6,%7}, {%8,%9}, {%0,%1,%2,%3};"
        : "+f"(d[0]), "+f"(d[1]), "+f"(d[2]), "+f"(d[3])
        : "r"(a[0]), "r"(a[1]), "r"(a[2]), "r"(a[3]), "r"(b[0]), "r"(b[1]));
}

// ldmatrix x4: each group of 8 lanes supplies row addresses of one 8x8-b16
// (= 8x4-float) tile; result reg j is distributed as [lane>>2][lane&3] of tile j.
__device__ __forceinline__ void ldsm_x4(uint32_t addr, uint32_t* r) {
    asm volatile("ldmatrix.sync.aligned.m8n8.x4.shared.b16 {%0,%1,%2,%3}, [%4];"
                 : "=r"(r[0]), "=r"(r[1]), "=r"(r[2]), "=r"(r[3]) : "r"(addr));
}

// ---------------------------------------------------------------------------
// Kernel 0: zero d_out
// ---------------------------------------------------------------------------
__global__ void k_zero(float4* p, size_t n4) {
    size_t i = (size_t)blockIdx.x * blockDim.x + threadIdx.x;
    size_t stride = (size_t)gridDim.x * blockDim.x;
    float4 z = make_float4(0.f, 0.f, 0.f, 0.f);
    for (; i < n4; i += stride) p[i] = z;
}

// ---------------------------------------------------------------------------
// Kernel 1: router scores (exact fp32) — one warp per token
// ---------------------------------------------------------------------------
__global__ void k_router(const float* __restrict__ x, const float* __restrict__ wr,
                         const float* __restrict__ br) {
    int gw   = (blockIdx.x * blockDim.x + threadIdx.x) >> 5;
    int lane = threadIdx.x & 31;
    if (gw >= B_ * L_) return;
    const float4* row = (const float4*)(x + (size_t)gw * D_);
    const float4* w   = (const float4*)wr;
    float acc = 0.f;
    #pragma unroll 4
    for (int i = lane; i < D_ / 4; i += 32) {
        float4 a = row[i], b = w[i];
        acc += a.x * b.x + a.y * b.y + a.z * b.z + a.w * b.w;
    }
    #pragma unroll
    for (int o = 16; o; o >>= 1) acc += __shfl_xor_sync(0xffffffff, acc, o);
    if (lane == 0) g_scores[gw] = acc + br[0];
}

// ---------------------------------------------------------------------------
// Kernel 2: per-batch k-th-largest threshold via SMEM bitonic sort
// ---------------------------------------------------------------------------
__global__ void k_topk() {
    __shared__ float s[L_];
    int b = blockIdx.x, tid = threadIdx.x;
    for (int i = tid; i < L_; i += blockDim.x) s[i] = g_scores[b * L_ + i];
    __syncthreads();
    for (int size = 2; size <= L_; size <<= 1) {
        for (int stride = size >> 1; stride > 0; stride >>= 1) {
            for (int t = tid; t < L_; t += blockDim.x) {
                int p = t ^ stride;
                if (p > t) {
                    bool up = ((t & size) == 0);
                    float a = s[t], c = s[p];
                    if (up ? (a > c) : (a < c)) { s[t] = c; s[p] = a; }
                }
            }
            __syncthreads();
        }
    }
    if (tid == 0) { g_thr[b] = s[L_ - KCAP]; g_cnt[b] = 0; }
}

// ---------------------------------------------------------------------------
// Kernels 3/4: compact selected-index list (order irrelevant for correctness)
// ---------------------------------------------------------------------------
__global__ void k_sel_gt() {
    int i = blockIdx.x * blockDim.x + threadIdx.x;
    if (i >= B_ * L_) return;
    int b = i >> 12;
    if (g_scores[i] > g_thr[b]) {
        int p = atomicAdd(&g_cnt[b], 1);
        g_idx[b * KCAP + p] = i & (L_ - 1);
    }
}
__global__ void k_sel_eq() {
    int i = blockIdx.x * blockDim.x + threadIdx.x;
    if (i >= B_ * L_) return;
    int b = i >> 12;
    if (g_scores[i] == g_thr[b]) {
        int p = atomicAdd(&g_cnt[b], 1);
        if (p < KCAP) g_idx[b * KCAP + p] = i & (L_ - 1);
    }
}

// ---------------------------------------------------------------------------
// Kernel 5: gather selected tokens (+ RNA tf32 rounding for the GEMM)
// ---------------------------------------------------------------------------
__global__ void k_gather(const float* __restrict__ x) {
    int r   = blockIdx.x;
    int b   = r >> 11;
    int tok = g_idx[r];
    const float4* src = (const float4*)(x + ((size_t)(b * L_ + tok)) * D_);
    float4*       dst = (float4*)(g_xsel + (size_t)r * D_);
    for (int i = threadIdx.x; i < D_ / 4; i += blockDim.x) {
        float4 v = src[i];
        v.x = to_tf32(v.x); v.y = to_tf32(v.y); v.z = to_tf32(v.z); v.w = to_tf32(v.w);
        dst[i] = v;
    }
}

// ---------------------------------------------------------------------------
// Kernel 6: transpose weights to K-major (+ RNA tf32 rounding)
// ---------------------------------------------------------------------------
__global__ void k_transpose(const float* __restrict__ src, int R, int C, int which) {
    __shared__ float t[32][33];
    float* dst = which ? g_w2t : g_w1t;
    int c0 = blockIdx.x * 32, r0 = blockIdx.y * 32;
    for (int j = threadIdx.y; j < 32; j += 8)
        t[j][threadIdx.x] = src[(size_t)(r0 + j) * C + c0 + threadIdx.x];
    __syncthreads();
    for (int j = threadIdx.y; j < 32; j += 8)
        dst[(size_t)(c0 + j) * R + r0 + threadIdx.x] = to_tf32(t[threadIdx.x][j]);
}

// ---------------------------------------------------------------------------
// Kernel 7: tf32 mma.sync GEMM   C[M,N] = A[M,K] * Bt[N,K]^T   (+bias epilogue)
//   mode 0: A=g_xsel, Bt=g_w1t, epilogue gelu -> g_h (tf32-rounded)
//   mode 1: A=g_h,    Bt=g_w2t, epilogue bias -> scatter to out via g_idx
// CTA 128x128x32, 128 threads, 4 warps (2x2) each computing 64x64.
// 3-stage cp.async ring, one __syncthreads per k-tile.
// Fragment loads via ldmatrix.x4 (32 LDSM per warp-k-tile vs 128 scalar LDS).
// 144B SMEM rows -> conflict-free 8-row LDSM phases. 2 CTAs/SM.
// ---------------------------------------------------------------------------
#define TK 32
#define SROW 36                      // floats per SMEM row (32 data + 4 pad)
#define A_BYTES (128 * SROW * 4)     // 18432
#define STAGE_BYTES (2 * A_BYTES)    // 36864 (A then B)
#define NSTAGE 3
#define SM_TOTAL (NSTAGE * STAGE_BYTES)  // 110592

__device__ __forceinline__ void prefetch_stage(
    uint32_t sb, int stage, const float* __restrict__ A, const float* __restrict__ Bt,
    size_t rowA0, size_t rowB0, int Ktot, int k0, int tid)
{
    uint32_t base = sb + stage * STAGE_BYTES;
    #pragma unroll
    for (int j = 0; j < 8; j++) {
        int c = j * 128 + tid;
        int r = c >> 3, q = c & 7;
        const float* ga = A  + (rowA0 + (size_t)r) * (size_t)Ktot + k0 + q * 4;
        const float* gb = Bt + (rowB0 + (size_t)r) * (size_t)Ktot + k0 + q * 4;
        uint32_t sa = base + (uint32_t)(r * 144 + q * 16);
        uint32_t sbb = sa + A_BYTES;
        asm volatile("cp.async.cg.shared.global [%0], [%1], 16;" :: "r"(sa),  "l"(ga) : "memory");
        asm volatile("cp.async.cg.shared.global [%0], [%1], 16;" :: "r"(sbb), "l"(gb) : "memory");
    }
}

__global__ __launch_bounds__(128) void k_gemm(
    const float* __restrict__ bias, float* __restrict__ out,
    int Ktot, int Ntot, int mode)
{
    extern __shared__ char smem[];
    uint32_t sb = cvta_smem(smem);
    int tid  = threadIdx.x;
    int wid  = tid >> 5;
    int lane = tid & 31;
    int wm   = wid & 1;                       // warp M index (0/1)
    int wn   = wid >> 1;                      // warp N index (0/1)

    const float* A  = (mode == 0) ? g_xsel : g_h;
    const float* Bt = (mode == 0) ? g_w1t  : g_w2t;

    const size_t rowA0 = (size_t)blockIdx.y * 128;
    const size_t colB0 = (size_t)blockIdx.x * 128;
    const int NS = Ktot / TK;

    float acc[4][8][4];
    #pragma unroll
    for (int mi = 0; mi < 4; mi++)
        #pragma unroll
        for (int ni = 0; ni < 8; ni++)
            #pragma unroll
            for (int j = 0; j < 4; j++) acc[mi][ni][j] = 0.f;

    // ldmatrix lane-offset tables (bytes from stage base).
    // A tile mi (x4): reg0 rows +0..7 col kb | reg1 rows +8..15 col kb
    //                 reg2 rows +0..7 col kb+4 | reg3 rows +8..15 col kb+4
    // B pair p (x4):  reg0 = b0(ni=2p), reg1 = b1(ni=2p),
    //                 reg2 = b0(ni=2p+1), reg3 = b1(ni=2p+1)
    const int g  = lane >> 3;    // 0..3 (tile select within x4)
    const int rr = lane & 7;     // row within tile
    uint32_t laneA[4], laneB[4];
    #pragma unroll
    for (int mi = 0; mi < 4; mi++)
        laneA[mi] = (uint32_t)(((wm * 64 + mi * 16 + (g & 1) * 8 + rr) * SROW
                                + (g >> 1) * 4) * 4);
    #pragma unroll
    for (int p = 0; p < 4; p++)
        laneB[p] = (uint32_t)(((wn * 64 + p * 16 + (g >> 1) * 8 + rr) * SROW
                               + (g & 1) * 4) * 4) + A_BYTES;

    // prologue: stages 0, 1 in flight
    prefetch_stage(sb, 0, A, Bt, rowA0, colB0, Ktot, 0, tid);
    asm volatile("cp.async.commit_group;" ::: "memory");
    prefetch_stage(sb, 1, A, Bt, rowA0, colB0, Ktot, TK, tid);
    asm volatile("cp.async.commit_group;" ::: "memory");

    int buf = 0;                // = s % 3
    for (int s = 0; s < NS; s++) {
        asm volatile("cp.async.wait_group 1;" ::: "memory");
        __syncthreads();        // stage s ready; buffer (s+2)%3 free since iter s-1

        // refill the ring 2 tiles ahead, BEFORE issuing this tile's MMAs
        if (s + 2 < NS) {
            int nbuf = buf + 2; if (nbuf >= NSTAGE) nbuf -= NSTAGE;
            prefetch_stage(sb, nbuf, A, Bt, rowA0, colB0, Ktot, (s + 2) * TK, tid);
        }
        asm volatile("cp.async.commit_group;" ::: "memory");

        const uint32_t stageBase = sb + (uint32_t)(buf * STAGE_BYTES);

        #pragma unroll
        for (int ks = 0; ks < 4; ks++) {
            const uint32_t koff = (uint32_t)(ks * 32);   // 8 floats = 32B
            uint32_t afr[4][4];
            uint32_t bfr[4][4];
            #pragma unroll
            for (int mi = 0; mi < 4; mi++) ldsm_x4(stageBase + laneA[mi] + koff, afr[mi]);
            #pragma unroll
            for (int p = 0; p < 4; p++)    ldsm_x4(stageBase + laneB[p] + koff, bfr[p]);
            #pragma unroll
            for (int mi = 0; mi < 4; mi++)
                #pragma unroll
                for (int ni = 0; ni < 8; ni++)
                    mma1688(acc[mi][ni], afr[mi], &bfr[ni >> 1][(ni & 1) * 2]);
        }

        buf++; if (buf >= NSTAGE) buf -= NSTAGE;
    }

    // ------------------------- epilogue -------------------------
    // accum layout m16n8: c0/c1 at (row lr, col 2*lc / 2*lc+1), c2/c3 at row lr+8
    const int lr = lane >> 2;
    const int lc = lane & 3;
    #pragma unroll
    for (int mi = 0; mi < 4; mi++) {
        size_t m0 = rowA0 + (size_t)(wm * 64 + mi * 16 + lr);
        size_t m1 = m0 + 8;
        if (mode == 0) {
            float* row0 = g_h + m0 * (size_t)Ntot;
            float* row1 = g_h + m1 * (size_t)Ntot;
            #pragma unroll
            for (int ni = 0; ni < 8; ni++) {
                size_t col = colB0 + wn * 64 + ni * 8 + lc * 2;
                float b0 = bias[col], b1 = bias[col + 1];
                float2 v0, v1;
                v0.x = to_tf32(gelu_tanh(acc[mi][ni][0] + b0));
                v0.y = to_tf32(gelu_tanh(acc[mi][ni][1] + b1));
                v1.x = to_tf32(gelu_tanh(acc[mi][ni][2] + b0));
                v1.y = to_tf32(gelu_tanh(acc[mi][ni][3] + b1));
                *(float2*)(row0 + col) = v0;
                *(float2*)(row1 + col) = v1;
            }
        } else {
            int tok0 = g_idx[m0], tok1 = g_idx[m1];
            int b0i = (int)(m0 >> 11), b1i = (int)(m1 >> 11);
            float* row0 = out + ((size_t)(b0i * L_ + tok0)) * D_;
            float* row1 = out + ((size_t)(b1i * L_ + tok1)) * D_;
            #pragma unroll
            for (int ni = 0; ni < 8; ni++) {
                size_t col = colB0 + wn * 64 + ni * 8 + lc * 2;
                float b0 = bias[col], b1 = bias[col + 1];
                float2 v0, v1;
                v0.x = acc[mi][ni][0] + b0;
                v0.y = acc[mi][ni][1] + b1;
                v1.x = acc[mi][ni][2] + b0;
                v1.y = acc[mi][ni][3] + b1;
                *(float2*)(row0 + col) = v0;
                *(float2*)(row1 + col) = v1;
            }
        }
    }
}

// ---------------------------------------------------------------------------
// Host entry
// ---------------------------------------------------------------------------
extern "C" void kernel_launch(void* const* d_in, const int* in_sizes, int n_in,
                              void* d_out, int out_size) {
    (void)in_sizes; (void)n_in;
    const float* x  = (const float*)d_in[0];
    const float* wr = (const float*)d_in[1];
    const float* br = (const float*)d_in[2];
    const float* w1 = (const float*)d_in[3];
    const float* b1 = (const float*)d_in[4];
    const float* w2 = (const float*)d_in[5];
    const float* b2 = (const float*)d_in[6];
    float* out = (float*)d_out;

    // 0) zero output (poisoned by harness)
    k_zero<<<2048, 256>>>((float4*)out, (size_t)out_size / 4);

    // 1) router scores (fp32 exact)
    k_router<<<(B_ * L_ * 32) / 256, 256>>>(x, wr, br);

    // 2) per-batch threshold + counter reset
    k_topk<<<B_, 1024>>>();

    // 3/4) selection -> compact index list
    k_sel_gt<<<(B_ * L_) / 256, 256>>>();
    k_sel_eq<<<(B_ * L_) / 256, 256>>>();

    // 5) gather selected tokens (tf32-rounded)
    k_gather<<<BK, 256>>>(x);

    // 6) transpose weights to K-major (tf32-rounded)
    dim3 tb(32, 8);
    k_transpose<<<dim3(DF_ / 32, D_ / 32), tb>>>(w1, D_, DF_, 0);   // -> g_w1t [DF,D]
    k_transpose<<<dim3(D_ / 32, DF_ / 32), tb>>>(w2, DF_, D_, 1);   // -> g_w2t [D,DF]

    // 7) FFN GEMMs (mma.sync tf32 + ldmatrix fragment loads)
    static int smem_set = 0;
    if (!smem_set) {
        cudaFuncSetAttribute(k_gemm, cudaFuncAttributeMaxDynamicSharedMemorySize, SM_TOTAL);
        smem_set = 1;
    }
    k_gemm<<<dim3(DF_ / 128, BK / 128), 128, SM_TOTAL>>>(b1, out, D_,  DF_, 0);
    k_gemm<<<dim3(D_  / 128, BK / 128), 128, SM_TOTAL>>>(b2, out, DF_, D_,  1);
}

// round 11
// speedup vs baseline: 1.0130x; 1.0130x over previous
#include <cuda_runtime.h>
#include <cstdint>
#include <cstddef>

// Problem constants
#define B_   4
#define L_   4096
#define D_   2048
#define DF_  8192
#define KCAP 2048              // L * 0.5
#define BK   (B_ * KCAP)       // 8192 selected rows total

// ---------------------------------------------------------------------------
// Device scratch (static globals: allocation-free per harness rules)
// ---------------------------------------------------------------------------
__device__ float g_scores[B_ * L_];
__device__ float g_thr[B_];
__device__ int   g_cnt[B_];
__device__ int   g_idx[BK];
__device__ float g_xsel[(size_t)BK * D_];    //  64 MB (tf32-rounded)
__device__ float g_h   [(size_t)BK * DF_];   // 256 MB (tf32-rounded)
__device__ float g_w1t [(size_t)DF_ * D_];   //  64 MB (W1^T K-major, tf32-rounded)
__device__ float g_w2t [(size_t)D_ * DF_];   //  64 MB (W2^T K-major, tf32-rounded)

// ---------------------------------------------------------------------------
// Helpers
// ---------------------------------------------------------------------------
__device__ __forceinline__ uint32_t cvta_smem(const void* p) {
    uint32_t a;
    asm("{ .reg .u64 t; cvta.to.shared.u64 t, %1; cvt.u32.u64 %0, t; }"
        : "=r"(a) : "l"(p));
    return a;
}

__device__ __forceinline__ float to_tf32(float x) {
    uint32_t u;
    asm("cvt.rna.tf32.f32 %0, %1;" : "=r"(u) : "f"(x));
    return __uint_as_float(u);
}

__device__ __forceinline__ float gelu_tanh(float x) {
    float x3 = x * x * x;
    float t  = tanhf(0.7978845608028654f * (x + 0.044715f * x3));
    return 0.5f * x * (1.0f + t);
}

__device__ __forceinline__ void mma1688(float* d, const uint32_t* a, const uint32_t* b) {
    asm volatile(
        "mma.sync.aligned.m16n8k8.row.col.f32.tf32.tf32.f32 "
        "{%0,%1,%2,%3}, {%4,%5,%6,%7}, {%8,%9}, {%0,%1,%2,%3};"
        : "+f"(d[0]), "+f"(d[1]), "+f"(d[2]), "+f"(d[3])
        : "r"(a[0]), "r"(a[1]), "r"(a[2]), "r"(a[3]), "r"(b[0]), "r"(b[1]));
}

// ---------------------------------------------------------------------------
// Kernel 0: zero d_out
// ---------------------------------------------------------------------------
__global__ void k_zero(float4* p, size_t n4) {
    size_t i = (size_t)blockIdx.x * blockDim.x + threadIdx.x;
    size_t stride = (size_t)gridDim.x * blockDim.x;
    float4 z = make_float4(0.f, 0.f, 0.f, 0.f);
    for (; i < n4; i += stride) p[i] = z;
}

// ---------------------------------------------------------------------------
// Kernel 1: router scores (exact fp32) — one warp per token
// ---------------------------------------------------------------------------
__global__ void k_router(const float* __restrict__ x, const float* __restrict__ wr,
                         const float* __restrict__ br) {
    int gw   = (blockIdx.x * blockDim.x + threadIdx.x) >> 5;
    int lane = threadIdx.x & 31;
    if (gw >= B_ * L_) return;
    const float4* row = (const float4*)(x + (size_t)gw * D_);
    const float4* w   = (const float4*)wr;
    float acc = 0.f;
    #pragma unroll 4
    for (int i = lane; i < D_ / 4; i += 32) {
        float4 a = row[i], b = w[i];
        acc += a.x * b.x + a.y * b.y + a.z * b.z + a.w * b.w;
    }
    #pragma unroll
    for (int o = 16; o; o >>= 1) acc += __shfl_xor_sync(0xffffffff, acc, o);
    if (lane == 0) g_scores[gw] = acc + br[0];
}

// ---------------------------------------------------------------------------
// Kernel 2: per-batch k-th-largest threshold via SMEM bitonic sort
// ---------------------------------------------------------------------------
__global__ void k_topk() {
    __shared__ float s[L_];
    int b = blockIdx.x, tid = threadIdx.x;
    for (int i = tid; i < L_; i += blockDim.x) s[i] = g_scores[b * L_ + i];
    __syncthreads();
    for (int size = 2; size <= L_; size <<= 1) {
        for (int stride = size >> 1; stride > 0; stride >>= 1) {
            for (int t = tid; t < L_; t += blockDim.x) {
                int p = t ^ stride;
                if (p > t) {
                    bool up = ((t & size) == 0);
                    float a = s[t], c = s[p];
                    if (up ? (a > c) : (a < c)) { s[t] = c; s[p] = a; }
                }
            }
            __syncthreads();
        }
    }
    if (tid == 0) { g_thr[b] = s[L_ - KCAP]; g_cnt[b] = 0; }
}

// ---------------------------------------------------------------------------
// Kernels 3/4: compact selected-index list (order irrelevant for correctness)
// ---------------------------------------------------------------------------
__global__ void k_sel_gt() {
    int i = blockIdx.x * blockDim.x + threadIdx.x;
    if (i >= B_ * L_) return;
    int b = i >> 12;
    if (g_scores[i] > g_thr[b]) {
        int p = atomicAdd(&g_cnt[b], 1);
        g_idx[b * KCAP + p] = i & (L_ - 1);
    }
}
__global__ void k_sel_eq() {
    int i = blockIdx.x * blockDim.x + threadIdx.x;
    if (i >= B_ * L_) return;
    int b = i >> 12;
    if (g_scores[i] == g_thr[b]) {
        int p = atomicAdd(&g_cnt[b], 1);
        if (p < KCAP) g_idx[b * KCAP + p] = i & (L_ - 1);
    }
}

// ---------------------------------------------------------------------------
// Kernel 5: gather selected tokens (+ RNA tf32 rounding for the GEMM)
// ---------------------------------------------------------------------------
__global__ void k_gather(const float* __restrict__ x) {
    int r   = blockIdx.x;
    int b   = r >> 11;
    int tok = g_idx[r];
    const float4* src = (const float4*)(x + ((size_t)(b * L_ + tok)) * D_);
    float4*       dst = (float4*)(g_xsel + (size_t)r * D_);
    for (int i = threadIdx.x; i < D_ / 4; i += blockDim.x) {
        float4 v = src[i];
        v.x = to_tf32(v.x); v.y = to_tf32(v.y); v.z = to_tf32(v.z); v.w = to_tf32(v.w);
        dst[i] = v;
    }
}

// ---------------------------------------------------------------------------
// Kernel 6: transpose weights to K-major (+ RNA tf32 rounding)
// ---------------------------------------------------------------------------
__global__ void k_transpose(const float* __restrict__ src, int R, int C, int which) {
    __shared__ float t[32][33];
    float* dst = which ? g_w2t : g_w1t;
    int c0 = blockIdx.x * 32, r0 = blockIdx.y * 32;
    for (int j = threadIdx.y; j < 32; j += 8)
        t[j][threadIdx.x] = src[(size_t)(r0 + j) * C + c0 + threadIdx.x];
    __syncthreads();
    for (int j = threadIdx.y; j < 32; j += 8)
        dst[(size_t)(c0 + j) * R + r0 + threadIdx.x] = to_tf32(t[threadIdx.x][j]);
}

// ---------------------------------------------------------------------------
// Kernel 7: tf32 mma.sync GEMM   C[M,N] = A[M,K] * Bt[N,K]^T   (+bias epilogue)
//   mode 0: A=g_xsel, Bt=g_w1t, epilogue gelu -> g_h (tf32-rounded)
//   mode 1: A=g_h,    Bt=g_w2t, epilogue bias -> scatter to out via g_idx
// CTA 128x128x32 tile, 256 threads, 8 warps (2 M x 4 N), warp tile 64x32.
// acc = 64 regs/thread -> <=128 regs total -> 2 CTAs/SM -> 4 warps/SMSP
// (double the latency hiding of the 128-thread version).
// 3-stage cp.async ring, one __syncthreads per k-tile, scalar LDS fragments,
// 144B SMEM rows (conflict-free).
// ---------------------------------------------------------------------------
#define TK 32
#define SROW 36                      // floats per SMEM row (32 data + 4 pad)
#define A_BYTES (128 * SROW * 4)     // 18432
#define STAGE_BYTES (2 * A_BYTES)    // 36864 (A then B)
#define NSTAGE 3
#define SM_TOTAL (NSTAGE * STAGE_BYTES)  // 110592

__device__ __forceinline__ void prefetch_stage(
    uint32_t sb, int stage, const float* __restrict__ A, const float* __restrict__ Bt,
    size_t rowA0, size_t rowB0, int Ktot, int k0, int tid)
{
    uint32_t base = sb + stage * STAGE_BYTES;
    #pragma unroll
    for (int j = 0; j < 4; j++) {               // 256 threads: 4 iters cover 128 rows
        int c = j * 256 + tid;
        int r = c >> 3, q = c & 7;
        const float* ga = A  + (rowA0 + (size_t)r) * (size_t)Ktot + k0 + q * 4;
        const float* gb = Bt + (rowB0 + (size_t)r) * (size_t)Ktot + k0 + q * 4;
        uint32_t sa = base + (uint32_t)(r * 144 + q * 16);
        uint32_t sbb = sa + A_BYTES;
        asm volatile("cp.async.cg.shared.global [%0], [%1], 16;" :: "r"(sa),  "l"(ga) : "memory");
        asm volatile("cp.async.cg.shared.global [%0], [%1], 16;" :: "r"(sbb), "l"(gb) : "memory");
    }
}

__global__ __launch_bounds__(256, 2) void k_gemm(
    const float* __restrict__ bias, float* __restrict__ out,
    int Ktot, int Ntot, int mode)
{
    extern __shared__ char smem[];
    uint32_t sb = cvta_smem(smem);
    int tid  = threadIdx.x;
    int wid  = tid >> 5;
    int lane = tid & 31;
    int wm   = wid & 1;                       // warp M index (0/1), 64 rows each
    int wn   = wid >> 1;                      // warp N index (0..3), 32 cols each

    const float* A  = (mode == 0) ? g_xsel : g_h;
    const float* Bt = (mode == 0) ? g_w1t  : g_w2t;

    const size_t rowA0 = (size_t)blockIdx.y * 128;
    const size_t colB0 = (size_t)blockIdx.x * 128;
    const int NS = Ktot / TK;

    float acc[4][4][4];
    #pragma unroll
    for (int mi = 0; mi < 4; mi++)
        #pragma unroll
        for (int ni = 0; ni < 4; ni++)
            #pragma unroll
            for (int j = 0; j < 4; j++) acc[mi][ni][j] = 0.f;

    // prologue: stages 0, 1 in flight
    prefetch_stage(sb, 0, A, Bt, rowA0, colB0, Ktot, 0, tid);
    asm volatile("cp.async.commit_group;" ::: "memory");
    prefetch_stage(sb, 1, A, Bt, rowA0, colB0, Ktot, TK, tid);
    asm volatile("cp.async.commit_group;" ::: "memory");

    const int lr = lane >> 2;   // 0..7
    const int lc = lane & 3;    // 0..3

    int buf = 0;                // = s % 3
    for (int s = 0; s < NS; s++) {
        asm volatile("cp.async.wait_group 1;" ::: "memory");
        __syncthreads();        // stage s ready; buffer (s+2)%3 free since iter s-1

        // refill the ring 2 tiles ahead, BEFORE issuing this tile's MMAs
        if (s + 2 < NS) {
            int nbuf = buf + 2; if (nbuf >= NSTAGE) nbuf -= NSTAGE;
            prefetch_stage(sb, nbuf, A, Bt, rowA0, colB0, Ktot, (s + 2) * TK, tid);
        }
        asm volatile("cp.async.commit_group;" ::: "memory");

        const float* sA = (const float*)(smem + buf * STAGE_BYTES);
        const float* sB = (const float*)(smem + buf * STAGE_BYTES + A_BYTES);

        #pragma unroll
        for (int ks = 0; ks < 4; ks++) {
            int kb = ks * 8;
            uint32_t afr[4][4];
            uint32_t bfr[4][2];
            #pragma unroll
            for (int mi = 0; mi < 4; mi++) {
                int r = wm * 64 + mi * 16 + lr;
                int c = kb + lc;
                afr[mi][0] = __float_as_uint(sA[r * SROW + c]);
                afr[mi][1] = __float_as_uint(sA[(r + 8) * SROW + c]);
                afr[mi][2] = __float_as_uint(sA[r * SROW + c + 4]);
                afr[mi][3] = __float_as_uint(sA[(r + 8) * SROW + c + 4]);
            }
            #pragma unroll
            for (int ni = 0; ni < 4; ni++) {
                int n = wn * 32 + ni * 8 + lr;
                bfr[ni][0] = __float_as_uint(sB[n * SROW + kb + lc]);
                bfr[ni][1] = __float_as_uint(sB[n * SROW + kb + 4 + lc]);
            }
            #pragma unroll
            for (int mi = 0; mi < 4; mi++)
                #pragma unroll
                for (int ni = 0; ni < 4; ni++)
                    mma1688(acc[mi][ni], afr[mi], bfr[ni]);
        }

        buf++; if (buf >= NSTAGE) buf -= NSTAGE;
    }

    // ------------------------- epilogue -------------------------
    // accum layout m16n8: c0/c1 at (row lr, col 2*lc / 2*lc+1), c2/c3 at row lr+8
    #pragma unroll
    for (int mi = 0; mi < 4; mi++) {
        size_t m0 = rowA0 + (size_t)(wm * 64 + mi * 16 + lr);
        size_t m1 = m0 + 8;
        if (mode == 0) {
            float* row0 = g_h + m0 * (size_t)Ntot;
            float* row1 = g_h + m1 * (size_t)Ntot;
            #pragma unroll
            for (int ni = 0; ni < 4; ni++) {
                size_t col = colB0 + wn * 32 + ni * 8 + lc * 2;
                float b0 = bias[col], b1 = bias[col + 1];
                float2 v0, v1;
                v0.x = to_tf32(gelu_tanh(acc[mi][ni][0] + b0));
                v0.y = to_tf32(gelu_tanh(acc[mi][ni][1] + b1));
                v1.x = to_tf32(gelu_tanh(acc[mi][ni][2] + b0));
                v1.y = to_tf32(gelu_tanh(acc[mi][ni][3] + b1));
                *(float2*)(row0 + col) = v0;
                *(float2*)(row1 + col) = v1;
            }
        } else {
            int tok0 = g_idx[m0], tok1 = g_idx[m1];
            int b0i = (int)(m0 >> 11), b1i = (int)(m1 >> 11);
            float* row0 = out + ((size_t)(b0i * L_ + tok0)) * D_;
            float* row1 = out + ((size_t)(b1i * L_ + tok1)) * D_;
            #pragma unroll
            for (int ni = 0; ni < 4; ni++) {
                size_t col = colB0 + wn * 32 + ni * 8 + lc * 2;
                float b0 = bias[col], b1 = bias[col + 1];
                float2 v0, v1;
                v0.x = acc[mi][ni][0] + b0;
                v0.y = acc[mi][ni][1] + b1;
                v1.x = acc[mi][ni][2] + b0;
                v1.y = acc[mi][ni][3] + b1;
                *(float2*)(row0 + col) = v0;
                *(float2*)(row1 + col) = v1;
            }
        }
    }
}

// ---------------------------------------------------------------------------
// Host entry
// ---------------------------------------------------------------------------
extern "C" void kernel_launch(void* const* d_in, const int* in_sizes, int n_in,
                              void* d_out, int out_size) {
    (void)in_sizes; (void)n_in;
    const float* x  = (const float*)d_in[0];
    const float* wr = (const float*)d_in[1];
    const float* br = (const float*)d_in[2];
    const float* w1 = (const float*)d_in[3];
    const float* b1 = (const float*)d_in[4];
    const float* w2 = (const float*)d_in[5];
    const float* b2 = (const float*)d_in[6];
    float* out = (float*)d_out;

    // 0) zero output (poisoned by harness)
    k_zero<<<2048, 256>>>((float4*)out, (size_t)out_size / 4);

    // 1) router scores (fp32 exact)
    k_router<<<(B_ * L_ * 32) / 256, 256>>>(x, wr, br);

    // 2) per-batch threshold + counter reset
    k_topk<<<B_, 1024>>>();

    // 3/4) selection -> compact index list
    k_sel_gt<<<(B_ * L_) / 256, 256>>>();
    k_sel_eq<<<(B_ * L_) / 256, 256>>>();

    // 5) gather selected tokens (tf32-rounded)
    k_gather<<<BK, 256>>>(x);

    // 6) transpose weights to K-major (tf32-rounded)
    dim3 tb(32, 8);
    k_transpose<<<dim3(DF_ / 32, D_ / 32), tb>>>(w1, D_, DF_, 0);   // -> g_w1t [DF,D]
    k_transpose<<<dim3(D_ / 32, DF_ / 32), tb>>>(w2, DF_, D_, 1);   // -> g_w2t [D,DF]

    // 7) FFN GEMMs (mma.sync tf32, 256 threads, 4 warps/SMSP)
    static int smem_set = 0;
    if (!smem_set) {
        cudaFuncSetAttribute(k_gemm, cudaFuncAttributeMaxDynamicSharedMemorySize, SM_TOTAL);
        smem_set = 1;
    }
    k_gemm<<<dim3(DF_ / 128, BK / 128), 256, SM_TOTAL>>>(b1, out, D_,  DF_, 0);
    k_gemm<<<dim3(D_  / 128, BK / 128), 256, SM_TOTAL>>>(b2, out, DF_, D_,  1);
}

// round 12
// speedup vs baseline: 1.9067x; 1.8822x over previous
#include <cuda_runtime.h>
#include <cuda_fp16.h>
#include <cstdint>
#include <cstddef>

// Problem constants
#define B_   4
#define L_   4096
#define D_   2048
#define DF_  8192
#define KCAP 2048              // L * 0.5
#define BK   (B_ * KCAP)       // 8192 selected rows total

// ---------------------------------------------------------------------------
// Device scratch (static globals: allocation-free per harness rules)
// ---------------------------------------------------------------------------
__device__ float  g_scores[B_ * L_];
__device__ int    g_idx[BK];
__device__ __half g_xsel[(size_t)BK * D_];    //  32 MB (fp16)
__device__ __half g_h   [(size_t)BK * DF_];   // 128 MB (fp16)
__device__ __half g_w1t [(size_t)DF_ * D_];   //  32 MB (W1^T: [DF, D] K-major fp16)
__device__ __half g_w2t [(size_t)D_ * DF_];   //  32 MB (W2^T: [D, DF] K-major fp16)

// ---------------------------------------------------------------------------
// Helpers
// ---------------------------------------------------------------------------
__device__ __forceinline__ uint32_t cvta_smem(const void* p) {
    uint32_t a;
    asm("{ .reg .u64 t; cvta.to.shared.u64 t, %1; cvt.u32.u64 %0, t; }"
        : "=r"(a) : "l"(p));
    return a;
}

__device__ __forceinline__ float gelu_tanh(float x) {
    float x3 = x * x * x;
    float t  = tanhf(0.7978845608028654f * (x + 0.044715f * x3));
    return 0.5f * x * (1.0f + t);
}

// fp16 HMMA, fp32 accumulate: 2048 MACs per instruction (2x tf32 m16n8k8)
__device__ __forceinline__ void mma16816(float* d, const uint32_t* a, const uint32_t* b) {
    asm volatile(
        "mma.sync.aligned.m16n8k16.row.col.f32.f16.f16.f32 "
        "{%0,%1,%2,%3}, {%4,%5,%6,%7}, {%8,%9}, {%0,%1,%2,%3};"
        : "+f"(d[0]), "+f"(d[1]), "+f"(d[2]), "+f"(d[3])
        : "r"(a[0]), "r"(a[1]), "r"(a[2]), "r"(a[3]), "r"(b[0]), "r"(b[1]));
}

// ---------------------------------------------------------------------------
// Kernel 0: zero d_out
// ---------------------------------------------------------------------------
__global__ void k_zero(float4* p, size_t n4) {
    size_t i = (size_t)blockIdx.x * blockDim.x + threadIdx.x;
    size_t stride = (size_t)gridDim.x * blockDim.x;
    float4 z = make_float4(0.f, 0.f, 0.f, 0.f);
    for (; i < n4; i += stride) p[i] = z;
}

// ---------------------------------------------------------------------------
// Kernel 1: router scores (exact fp32) — one warp per token
// ---------------------------------------------------------------------------
__global__ void k_router(const float* __restrict__ x, const float* __restrict__ wr,
                         const float* __restrict__ br) {
    int gw   = (blockIdx.x * blockDim.x + threadIdx.x) >> 5;
    int lane = threadIdx.x & 31;
    if (gw >= B_ * L_) return;
    const float4* row = (const float4*)(x + (size_t)gw * D_);
    const float4* w   = (const float4*)wr;
    float acc = 0.f;
    #pragma unroll 4
    for (int i = lane; i < D_ / 4; i += 32) {
        float4 a = row[i], b = w[i];
        acc += a.x * b.x + a.y * b.y + a.z * b.z + a.w * b.w;
    }
    #pragma unroll
    for (int o = 16; o; o >>= 1) acc += __shfl_xor_sync(0xffffffff, acc, o);
    if (lane == 0) g_scores[gw] = acc + br[0];
}

// ---------------------------------------------------------------------------
// Kernel 2: FUSED per-batch threshold (bitonic sort) + compact index build.
// One CTA per batch. Selection order is irrelevant to correctness.
// ---------------------------------------------------------------------------
__global__ void k_topksel() {
    __shared__ float s[L_];
    __shared__ int   cnt;
    int b = blockIdx.x, tid = threadIdx.x;
    for (int i = tid; i < L_; i += blockDim.x) s[i] = g_scores[b * L_ + i];
    __syncthreads();
    for (int size = 2; size <= L_; size <<= 1) {
        for (int stride = size >> 1; stride > 0; stride >>= 1) {
            for (int t = tid; t < L_; t += blockDim.x) {
                int p = t ^ stride;
                if (p > t) {
                    bool up = ((t & size) == 0);
                    float a = s[t], c = s[p];
                    if (up ? (a > c) : (a < c)) { s[t] = c; s[p] = a; }
                }
            }
            __syncthreads();
        }
    }
    float thr = s[L_ - KCAP];
    if (tid == 0) cnt = 0;
    __syncthreads();
    for (int i = tid; i < L_; i += blockDim.x) {
        if (g_scores[b * L_ + i] > thr) {
            int p = atomicAdd(&cnt, 1);
            g_idx[b * KCAP + p] = i;
        }
    }
    __syncthreads();
    for (int i = tid; i < L_; i += blockDim.x) {
        if (g_scores[b * L_ + i] == thr) {
            int p = atomicAdd(&cnt, 1);
            if (p < KCAP) g_idx[b * KCAP + p] = i;
        }
    }
}

// ---------------------------------------------------------------------------
// Kernel 3: gather selected tokens -> fp16
// ---------------------------------------------------------------------------
__global__ void k_gather(const float* __restrict__ x) {
    int r   = blockIdx.x;
    int b   = r >> 11;
    int tok = g_idx[r];
    const float4* src = (const float4*)(x + ((size_t)(b * L_ + tok)) * D_);
    __half2*      dst = (__half2*)(g_xsel + (size_t)r * D_);
    for (int i = threadIdx.x; i < D_ / 4; i += blockDim.x) {
        float4 v = src[i];
        dst[2 * i]     = __floats2half2_rn(v.x, v.y);
        dst[2 * i + 1] = __floats2half2_rn(v.z, v.w);
    }
}

// ---------------------------------------------------------------------------
// Kernel 4: transpose BOTH weights to K-major fp16 in ONE launch (z selects)
//   z=0: w1 [D,DF] -> g_w1t [DF,D]     (bx over DF/32=256, by over D/32=64)
//   z=1: w2 [DF,D] -> g_w2t [D,DF]     (bx over D/32=64,  by over DF/32=256)
// ---------------------------------------------------------------------------
__global__ void k_transpose_both(const float* __restrict__ w1,
                                 const float* __restrict__ w2) {
    __shared__ float t[32][33];
    const float* src; __half* dst; int R, C;
    if (blockIdx.z == 0) {
        if (blockIdx.y >= D_ / 32) return;
        src = w1; dst = g_w1t; R = D_; C = DF_;
    } else {
        if (blockIdx.x >= D_ / 32) return;
        src = w2; dst = g_w2t; R = DF_; C = D_;
    }
    int c0 = blockIdx.x * 32, r0 = blockIdx.y * 32;
    for (int j = threadIdx.y; j < 32; j += 8)
        t[j][threadIdx.x] = src[(size_t)(r0 + j) * C + c0 + threadIdx.x];
    __syncthreads();
    for (int j = threadIdx.y; j < 32; j += 8)
        dst[(size_t)(c0 + j) * R + r0 + threadIdx.x] = __float2half_rn(t[threadIdx.x][j]);
}

// ---------------------------------------------------------------------------
// Kernel 5/6: fp16 mma.sync GEMM   C[M,N] = A[M,K] * Bt[N,K]^T  (+bias epilogue)
//   mode 0: A=g_xsel, Bt=g_w1t, epilogue gelu -> g_h (fp16)
//   mode 1: A=g_h,    Bt=g_w2t, epilogue bias -> scatter fp32 to out via g_idx
// CTA 128x128, TK=64 halfs, 128 threads, 4 warps (2x2), warp tile 64x64.
// 3-stage cp.async ring (proven best), one __syncthreads per k-tile.
// 144B SMEM rows (72 halfs) -> conflict-free scalar b32 fragment loads.
// Half the HMMA / LDS / cp.async of the tf32 version per FLOP.
// ---------------------------------------------------------------------------
#define TKH 64                       // k per tile (halfs)
#define SROWH 72                     // halfs per SMEM row (64 data + 8 pad = 144B)
#define A_BYTES (128 * SROWH * 2)    // 18432
#define STAGE_BYTES (2 * A_BYTES)    // 36864 (A then B)
#define NSTAGE 3
#define SM_TOTAL (NSTAGE * STAGE_BYTES)  // 110592

__device__ __forceinline__ void prefetch_stage(
    uint32_t sb, int stage, const __half* __restrict__ A, const __half* __restrict__ Bt,
    size_t rowA0, size_t rowB0, int Ktot, int k0, int tid)
{
    uint32_t base = sb + stage * STAGE_BYTES;
    #pragma unroll
    for (int j = 0; j < 8; j++) {
        int c = j * 128 + tid;
        int r = c >> 3, q = c & 7;                    // 8 x 16B chunks per 128B row
        const __half* ga = A  + (rowA0 + (size_t)r) * (size_t)Ktot + k0 + q * 8;
        const __half* gb = Bt + (rowB0 + (size_t)r) * (size_t)Ktot + k0 + q * 8;
        uint32_t sa  = base + (uint32_t)(r * 144 + q * 16);
        uint32_t sbb = sa + A_BYTES;
        asm volatile("cp.async.cg.shared.global [%0], [%1], 16;" :: "r"(sa),  "l"(ga) : "memory");
        asm volatile("cp.async.cg.shared.global [%0], [%1], 16;" :: "r"(sbb), "l"(gb) : "memory");
    }
}

__global__ __launch_bounds__(128) void k_gemm(
    const float* __restrict__ bias, float* __restrict__ out,
    int Ktot, int Ntot, int mode)
{
    extern __shared__ char smem[];
    uint32_t sb = cvta_smem(smem);
    int tid  = threadIdx.x;
    int wid  = tid >> 5;
    int lane = tid & 31;
    int wm   = wid & 1;                       // warp M index (0/1)
    int wn   = wid >> 1;                      // warp N index (0/1)

    const __half* A  = (mode == 0) ? g_xsel : g_h;
    const __half* Bt = (mode == 0) ? g_w1t  : g_w2t;

    const size_t rowA0 = (size_t)blockIdx.y * 128;
    const size_t colB0 = (size_t)blockIdx.x * 128;
    const int NS = Ktot / TKH;

    float acc[4][8][4];
    #pragma unroll
    for (int mi = 0; mi < 4; mi++)
        #pragma unroll
        for (int ni = 0; ni < 8; ni++)
            #pragma unroll
            for (int j = 0; j < 4; j++) acc[mi][ni][j] = 0.f;

    // prologue: stages 0, 1 in flight
    prefetch_stage(sb, 0, A, Bt, rowA0, colB0, Ktot, 0, tid);
    asm volatile("cp.async.commit_group;" ::: "memory");
    prefetch_stage(sb, 1, A, Bt, rowA0, colB0, Ktot, TKH, tid);
    asm volatile("cp.async.commit_group;" ::: "memory");

    const int lr = lane >> 2;   // 0..7
    const int lc = lane & 3;    // 0..3

    int buf = 0;                // = s % 3
    for (int s = 0; s < NS; s++) {
        asm volatile("cp.async.wait_group 1;" ::: "memory");
        __syncthreads();        // stage s ready; buffer (s+2)%3 free since iter s-1

        if (s + 2 < NS) {
            int nbuf = buf + 2; if (nbuf >= NSTAGE) nbuf -= NSTAGE;
            prefetch_stage(sb, nbuf, A, Bt, rowA0, colB0, Ktot, (s + 2) * TKH, tid);
        }
        asm volatile("cp.async.commit_group;" ::: "memory");

        const __half* sA = (const __half*)(smem + buf * STAGE_BYTES);
        const __half* sB = (const __half*)(smem + buf * STAGE_BYTES + A_BYTES);

        #pragma unroll
        for (int ks = 0; ks < 4; ks++) {            // 4 x k16 = TKH
            int kb = ks * 16;                       // half index within row
            uint32_t afr[4][4];
            uint32_t bfr[8][2];
            // A fragments: a0=(lr, kb+2lc..+1) a1=(lr+8,...) a2=(lr, kb+8+2lc..) a3=(lr+8,...)
            #pragma unroll
            for (int mi = 0; mi < 4; mi++) {
                int r = wm * 64 + mi * 16 + lr;
                int c = kb + 2 * lc;
                afr[mi][0] = *(const uint32_t*)(sA + r * SROWH + c);
                afr[mi][1] = *(const uint32_t*)(sA + (r + 8) * SROWH + c);
                afr[mi][2] = *(const uint32_t*)(sA + r * SROWH + c + 8);
                afr[mi][3] = *(const uint32_t*)(sA + (r + 8) * SROWH + c + 8);
            }
            // B fragments: b0=(n=lr, kb+2lc..+1), b1=(n=lr, kb+8+2lc..+1)
            #pragma unroll
            for (int ni = 0; ni < 8; ni++) {
                int n = wn * 64 + ni * 8 + lr;
                int c = kb + 2 * lc;
                bfr[ni][0] = *(const uint32_t*)(sB + n * SROWH + c);
                bfr[ni][1] = *(const uint32_t*)(sB + n * SROWH + c + 8);
            }
            #pragma unroll
            for (int mi = 0; mi < 4; mi++)
                #pragma unroll
                for (int ni = 0; ni < 8; ni++)
                    mma16816(acc[mi][ni], afr[mi], bfr[ni]);
        }

        buf++; if (buf >= NSTAGE) buf -= NSTAGE;
    }

    // ------------------------- epilogue -------------------------
    // accum layout m16n8: c0/c1 at (row lr, col 2*lc / 2*lc+1), c2/c3 at row lr+8
    #pragma unroll
    for (int mi = 0; mi < 4; mi++) {
        size_t m0 = rowA0 + (size_t)(wm * 64 + mi * 16 + lr);
        size_t m1 = m0 + 8;
        if (mode == 0) {
            __half* row0 = g_h + m0 * (size_t)Ntot;
            __half* row1 = g_h + m1 * (size_t)Ntot;
            #pragma unroll
            for (int ni = 0; ni < 8; ni++) {
                size_t col = colB0 + wn * 64 + ni * 8 + lc * 2;
                float b0 = bias[col], b1 = bias[col + 1];
                *(__half2*)(row0 + col) = __floats2half2_rn(
                    gelu_tanh(acc[mi][ni][0] + b0), gelu_tanh(acc[mi][ni][1] + b1));
                *(__half2*)(row1 + col) = __floats2half2_rn(
                    gelu_tanh(acc[mi][ni][2] + b0), gelu_tanh(acc[mi][ni][3] + b1));
            }
        } else {
            int tok0 = g_idx[m0], tok1 = g_idx[m1];
            int b0i = (int)(m0 >> 11), b1i = (int)(m1 >> 11);
            float* row0 = out + ((size_t)(b0i * L_ + tok0)) * D_;
            float* row1 = out + ((size_t)(b1i * L_ + tok1)) * D_;
            #pragma unroll
            for (int ni = 0; ni < 8; ni++) {
                size_t col = colB0 + wn * 64 + ni * 8 + lc * 2;
                float b0 = bias[col], b1 = bias[col + 1];
                float2 v0, v1;
                v0.x = acc[mi][ni][0] + b0;
                v0.y = acc[mi][ni][1] + b1;
                v1.x = acc[mi][ni][2] + b0;
                v1.y = acc[mi][ni][3] + b1;
                *(float2*)(row0 + col) = v0;
                *(float2*)(row1 + col) = v1;
            }
        }
    }
}

// ---------------------------------------------------------------------------
// Host entry — GEMM1 is launch index 5 so ncu (-s 5 -c 1) captures it.
// ---------------------------------------------------------------------------
extern "C" void kernel_launch(void* const* d_in, const int* in_sizes, int n_in,
                              void* d_out, int out_size) {
    (void)in_sizes; (void)n_in;
    const float* x  = (const float*)d_in[0];
    const float* wr = (const float*)d_in[1];
    const float* br = (const float*)d_in[2];
    const float* w1 = (const float*)d_in[3];
    const float* b1 = (const float*)d_in[4];
    const float* w2 = (const float*)d_in[5];
    const float* b2 = (const float*)d_in[6];
    float* out = (float*)d_out;

    static int smem_set = 0;
    if (!smem_set) {
        cudaFuncSetAttribute(k_gemm, cudaFuncAttributeMaxDynamicSharedMemorySize, SM_TOTAL);
        smem_set = 1;
    }

    // 0) zero output (poisoned by harness)
    k_zero<<<2048, 256>>>((float4*)out, (size_t)out_size / 4);

    // 1) router scores (fp32 exact)
    k_router<<<(B_ * L_ * 32) / 256, 256>>>(x, wr, br);

    // 2) threshold + index build (fused)
    k_topksel<<<B_, 1024>>>();

    // 3) gather selected tokens -> fp16
    k_gather<<<BK, 256>>>(x);

    // 4) both weight transposes -> fp16 K-major (single launch)
    k_transpose_both<<<dim3(DF_ / 32, DF_ / 32, 2), dim3(32, 8)>>>(w1, w2);

    // 5/6) FFN GEMMs (fp16 mma.sync m16n8k16, fp32 accumulate)
    k_gemm<<<dim3(DF_ / 128, BK / 128), 128, SM_TOTAL>>>(b1, out, D_,  DF_, 0);
    k_gemm<<<dim3(D_  / 128, BK / 128), 128, SM_TOTAL>>>(b2, out, DF_, D_,  1);
}

// round 13
// speedup vs baseline: 1.9564x; 1.0261x over previous
#include <cuda_runtime.h>
#include <cuda_fp16.h>
#include <cstdint>
#include <cstddef>

// Problem constants
#define B_   4
#define L_   4096
#define D_   2048
#define DF_  8192
#define KCAP 2048              // L * 0.5
#define BK   (B_ * KCAP)       // 8192 selected rows total

// ---------------------------------------------------------------------------
// Device scratch (static globals: allocation-free per harness rules)
// ---------------------------------------------------------------------------
__device__ float  g_scores[B_ * L_];
__device__ int    g_idx[BK];
__device__ __half g_xsel[(size_t)BK * D_];    //  32 MB (fp16)
__device__ __half g_h   [(size_t)BK * DF_];   // 128 MB (fp16)
__device__ __half g_w1t [(size_t)DF_ * D_];   //  32 MB (W1^T: [DF, D] K-major fp16)
__device__ __half g_w2t [(size_t)D_ * DF_];   //  32 MB (W2^T: [D, DF] K-major fp16)

// ---------------------------------------------------------------------------
// Helpers
// ---------------------------------------------------------------------------
__device__ __forceinline__ uint32_t cvta_smem(const void* p) {
    uint32_t a;
    asm("{ .reg .u64 t; cvta.to.shared.u64 t, %1; cvt.u32.u64 %0, t; }"
        : "=r"(a) : "l"(p));
    return a;
}

__device__ __forceinline__ float gelu_tanh(float x) {
    float x3 = x * x * x;
    float t  = tanhf(0.7978845608028654f * (x + 0.044715f * x3));
    return 0.5f * x * (1.0f + t);
}

// fp16 HMMA, fp32 accumulate: 2048 MACs per instruction
__device__ __forceinline__ void mma16816(float* d, const uint32_t* a, const uint32_t* b) {
    asm volatile(
        "mma.sync.aligned.m16n8k16.row.col.f32.f16.f16.f32 "
        "{%0,%1,%2,%3}, {%4,%5,%6,%7}, {%8,%9}, {%0,%1,%2,%3};"
        : "+f"(d[0]), "+f"(d[1]), "+f"(d[2]), "+f"(d[3])
        : "r"(a[0]), "r"(a[1]), "r"(a[2]), "r"(a[3]), "r"(b[0]), "r"(b[1]));
}

// ---------------------------------------------------------------------------
// k_zero: zero d_out (runs AFTER gemm1, BEFORE gemm2 — gemm1 never touches out)
// ---------------------------------------------------------------------------
__global__ void k_zero(float4* p, size_t n4) {
    size_t i = (size_t)blockIdx.x * blockDim.x + threadIdx.x;
    size_t stride = (size_t)gridDim.x * blockDim.x;
    float4 z = make_float4(0.f, 0.f, 0.f, 0.f);
    for (; i < n4; i += stride) p[i] = z;
}

// ---------------------------------------------------------------------------
// k_router: router scores (exact fp32) — one warp per token
// ---------------------------------------------------------------------------
__global__ void k_router(const float* __restrict__ x, const float* __restrict__ wr,
                         const float* __restrict__ br) {
    int gw   = (blockIdx.x * blockDim.x + threadIdx.x) >> 5;
    int lane = threadIdx.x & 31;
    if (gw >= B_ * L_) return;
    const float4* row = (const float4*)(x + (size_t)gw * D_);
    const float4* w   = (const float4*)wr;
    float acc = 0.f;
    #pragma unroll 4
    for (int i = lane; i < D_ / 4; i += 32) {
        float4 a = row[i], b = w[i];
        acc += a.x * b.x + a.y * b.y + a.z * b.z + a.w * b.w;
    }
    #pragma unroll
    for (int o = 16; o; o >>= 1) acc += __shfl_xor_sync(0xffffffff, acc, o);
    if (lane == 0) g_scores[gw] = acc + br[0];
}

// ---------------------------------------------------------------------------
// k_topksel: FUSED per-batch threshold (bitonic sort) + compact index build.
// ---------------------------------------------------------------------------
__global__ void k_topksel() {
    __shared__ float s[L_];
    __shared__ int   cnt;
    int b = blockIdx.x, tid = threadIdx.x;
    for (int i = tid; i < L_; i += blockDim.x) s[i] = g_scores[b * L_ + i];
    __syncthreads();
    for (int size = 2; size <= L_; size <<= 1) {
        for (int stride = size >> 1; stride > 0; stride >>= 1) {
            for (int t = tid; t < L_; t += blockDim.x) {
                int p = t ^ stride;
                if (p > t) {
                    bool up = ((t & size) == 0);
                    float a = s[t], c = s[p];
                    if (up ? (a > c) : (a < c)) { s[t] = c; s[p] = a; }
                }
            }
            __syncthreads();
        }
    }
    float thr = s[L_ - KCAP];
    if (tid == 0) cnt = 0;
    __syncthreads();
    for (int i = tid; i < L_; i += blockDim.x) {
        if (g_scores[b * L_ + i] > thr) {
            int p = atomicAdd(&cnt, 1);
            g_idx[b * KCAP + p] = i;
        }
    }
    __syncthreads();
    for (int i = tid; i < L_; i += blockDim.x) {
        if (g_scores[b * L_ + i] == thr) {
            int p = atomicAdd(&cnt, 1);
            if (p < KCAP) g_idx[b * KCAP + p] = i;
        }
    }
}

// ---------------------------------------------------------------------------
// k_prep: FUSED gather(->fp16) + both weight transposes (->fp16 K-major).
// Flat 1-D grid, 256 threads/block:
//   blocks [0, BK)                : gather row b
//   blocks [BK, BK+16384)         : w1 transpose tiles (bx over DF/32, by over D/32)
//   blocks [BK+16384, BK+32768)   : w2 transpose tiles (bx over D/32, by over DF/32)
// ---------------------------------------------------------------------------
#define NB_T1 ((DF_ / 32) * (D_ / 32))   // 16384
#define NB_T2 ((D_ / 32) * (DF_ / 32))   // 16384
#define NB_PREP (BK + NB_T1 + NB_T2)     // 40960

__global__ void k_prep(const float* __restrict__ x,
                       const float* __restrict__ w1,
                       const float* __restrict__ w2) {
    int blk = blockIdx.x;
    if (blk < BK) {
        // ---- gather selected token -> fp16 ----
        int r   = blk;
        int b   = r >> 11;
        int tok = g_idx[r];
        const float4* src = (const float4*)(x + ((size_t)(b * L_ + tok)) * D_);
        __half2*      dst = (__half2*)(g_xsel + (size_t)r * D_);
        for (int i = threadIdx.x; i < D_ / 4; i += blockDim.x) {
            float4 v = src[i];
            dst[2 * i]     = __floats2half2_rn(v.x, v.y);
            dst[2 * i + 1] = __floats2half2_rn(v.z, v.w);
        }
        return;
    }
    // ---- weight transpose tile ----
    __shared__ float t[32][33];
    const float* src; __half* dst; int R, C, bx, by;
    if (blk < BK + NB_T1) {
        int q = blk - BK;
        src = w1; dst = g_w1t; R = D_; C = DF_;
        bx = q % (DF_ / 32); by = q / (DF_ / 32);
    } else {
        int q = blk - BK - NB_T1;
        src = w2; dst = g_w2t; R = DF_; C = D_;
        bx = q % (D_ / 32); by = q / (D_ / 32);
    }
    int tx = threadIdx.x & 31, ty = threadIdx.x >> 5;   // 32 x 8
    int c0 = bx * 32, r0 = by * 32;
    for (int j = ty; j < 32; j += 8)
        t[j][tx] = src[(size_t)(r0 + j) * C + c0 + tx];
    __syncthreads();
    for (int j = ty; j < 32; j += 8)
        dst[(size_t)(c0 + j) * R + r0 + tx] = __float2half_rn(t[tx][j]);
}

// ---------------------------------------------------------------------------
// k_gemm: fp16 mma.sync GEMM  C[M,N] = A[M,K] * Bt[N,K]^T  (+bias epilogue)
//   mode 0: A=g_xsel, Bt=g_w1t, epilogue gelu -> g_h (fp16)
//   mode 1: A=g_h,    Bt=g_w2t, epilogue bias -> scatter fp32 to out via g_idx
// UNCHANGED from Round 12 (proven 1783us config).
// ---------------------------------------------------------------------------
#define TKH 64                       // k per tile (halfs)
#define SROWH 72                     // halfs per SMEM row (64 data + 8 pad = 144B)
#define A_BYTES (128 * SROWH * 2)    // 18432
#define STAGE_BYTES (2 * A_BYTES)    // 36864 (A then B)
#define NSTAGE 3
#define SM_TOTAL (NSTAGE * STAGE_BYTES)  // 110592

__device__ __forceinline__ void prefetch_stage(
    uint32_t sb, int stage, const __half* __restrict__ A, const __half* __restrict__ Bt,
    size_t rowA0, size_t rowB0, int Ktot, int k0, int tid)
{
    uint32_t base = sb + stage * STAGE_BYTES;
    #pragma unroll
    for (int j = 0; j < 8; j++) {
        int c = j * 128 + tid;
        int r = c >> 3, q = c & 7;                    // 8 x 16B chunks per 128B row
        const __half* ga = A  + (rowA0 + (size_t)r) * (size_t)Ktot + k0 + q * 8;
        const __half* gb = Bt + (rowB0 + (size_t)r) * (size_t)Ktot + k0 + q * 8;
        uint32_t sa  = base + (uint32_t)(r * 144 + q * 16);
        uint32_t sbb = sa + A_BYTES;
        asm volatile("cp.async.cg.shared.global [%0], [%1], 16;" :: "r"(sa),  "l"(ga) : "memory");
        asm volatile("cp.async.cg.shared.global [%0], [%1], 16;" :: "r"(sbb), "l"(gb) : "memory");
    }
}

__global__ __launch_bounds__(128) void k_gemm(
    const float* __restrict__ bias, float* __restrict__ out,
    int Ktot, int Ntot, int mode)
{
    extern __shared__ char smem[];
    uint32_t sb = cvta_smem(smem);
    int tid  = threadIdx.x;
    int wid  = tid >> 5;
    int lane = tid & 31;
    int wm   = wid & 1;                       // warp M index (0/1)
    int wn   = wid >> 1;                      // warp N index (0/1)

    const __half* A  = (mode == 0) ? g_xsel : g_h;
    const __half* Bt = (mode == 0) ? g_w1t  : g_w2t;

    const size_t rowA0 = (size_t)blockIdx.y * 128;
    const size_t colB0 = (size_t)blockIdx.x * 128;
    const int NS = Ktot / TKH;

    float acc[4][8][4];
    #pragma unroll
    for (int mi = 0; mi < 4; mi++)
        #pragma unroll
        for (int ni = 0; ni < 8; ni++)
            #pragma unroll
            for (int j = 0; j < 4; j++) acc[mi][ni][j] = 0.f;

    // prologue: stages 0, 1 in flight
    prefetch_stage(sb, 0, A, Bt, rowA0, colB0, Ktot, 0, tid);
    asm volatile("cp.async.commit_group;" ::: "memory");
    prefetch_stage(sb, 1, A, Bt, rowA0, colB0, Ktot, TKH, tid);
    asm volatile("cp.async.commit_group;" ::: "memory");

    const int lr = lane >> 2;   // 0..7
    const int lc = lane & 3;    // 0..3

    int buf = 0;                // = s % 3
    for (int s = 0; s < NS; s++) {
        asm volatile("cp.async.wait_group 1;" ::: "memory");
        __syncthreads();        // stage s ready; buffer (s+2)%3 free since iter s-1

        if (s + 2 < NS) {
            int nbuf = buf + 2; if (nbuf >= NSTAGE) nbuf -= NSTAGE;
            prefetch_stage(sb, nbuf, A, Bt, rowA0, colB0, Ktot, (s + 2) * TKH, tid);
        }
        asm volatile("cp.async.commit_group;" ::: "memory");

        const __half* sA = (const __half*)(smem + buf * STAGE_BYTES);
        const __half* sB = (const __half*)(smem + buf * STAGE_BYTES + A_BYTES);

        #pragma unroll
        for (int ks = 0; ks < 4; ks++) {            // 4 x k16 = TKH
            int kb = ks * 16;                       // half index within row
            uint32_t afr[4][4];
            uint32_t bfr[8][2];
            #pragma unroll
            for (int mi = 0; mi < 4; mi++) {
                int r = wm * 64 + mi * 16 + lr;
                int c = kb + 2 * lc;
                afr[mi][0] = *(const uint32_t*)(sA + r * SROWH + c);
                afr[mi][1] = *(const uint32_t*)(sA + (r + 8) * SROWH + c);
                afr[mi][2] = *(const uint32_t*)(sA + r * SROWH + c + 8);
                afr[mi][3] = *(const uint32_t*)(sA + (r + 8) * SROWH + c + 8);
            }
            #pragma unroll
            for (int ni = 0; ni < 8; ni++) {
                int n = wn * 64 + ni * 8 + lr;
                int c = kb + 2 * lc;
                bfr[ni][0] = *(const uint32_t*)(sB + n * SROWH + c);
                bfr[ni][1] = *(const uint32_t*)(sB + n * SROWH + c + 8);
            }
            #pragma unroll
            for (int mi = 0; mi < 4; mi++)
                #pragma unroll
                for (int ni = 0; ni < 8; ni++)
                    mma16816(acc[mi][ni], afr[mi], bfr[ni]);
        }

        buf++; if (buf >= NSTAGE) buf -= NSTAGE;
    }

    // ------------------------- epilogue -------------------------
    #pragma unroll
    for (int mi = 0; mi < 4; mi++) {
        size_t m0 = rowA0 + (size_t)(wm * 64 + mi * 16 + lr);
        size_t m1 = m0 + 8;
        if (mode == 0) {
            __half* row0 = g_h + m0 * (size_t)Ntot;
            __half* row1 = g_h + m1 * (size_t)Ntot;
            #pragma unroll
            for (int ni = 0; ni < 8; ni++) {
                size_t col = colB0 + wn * 64 + ni * 8 + lc * 2;
                float b0 = bias[col], b1 = bias[col + 1];
                *(__half2*)(row0 + col) = __floats2half2_rn(
                    gelu_tanh(acc[mi][ni][0] + b0), gelu_tanh(acc[mi][ni][1] + b1));
                *(__half2*)(row1 + col) = __floats2half2_rn(
                    gelu_tanh(acc[mi][ni][2] + b0), gelu_tanh(acc[mi][ni][3] + b1));
            }
        } else {
            int tok0 = g_idx[m0], tok1 = g_idx[m1];
            int b0i = (int)(m0 >> 11), b1i = (int)(m1 >> 11);
            float* row0 = out + ((size_t)(b0i * L_ + tok0)) * D_;
            float* row1 = out + ((size_t)(b1i * L_ + tok1)) * D_;
            #pragma unroll
            for (int ni = 0; ni < 8; ni++) {
                size_t col = colB0 + wn * 64 + ni * 8 + lc * 2;
                float b0 = bias[col], b1 = bias[col + 1];
                float2 v0, v1;
                v0.x = acc[mi][ni][0] + b0;
                v0.y = acc[mi][ni][1] + b1;
                v1.x = acc[mi][ni][2] + b0;
                v1.y = acc[mi][ni][3] + b1;
                *(float2*)(row0 + col) = v0;
                *(float2*)(row1 + col) = v1;
            }
        }
    }
}

// ---------------------------------------------------------------------------
// Host entry.
// Launch order (our idx): router(0) topksel(1) prep(2) GEMM1(3) zero(4) gemm2(5)
// The profiler slot (harness prelaunches + -s 5) lands on OUR idx 3 = GEMM1.
// ---------------------------------------------------------------------------
extern "C" void kernel_launch(void* const* d_in, const int* in_sizes, int n_in,
                              void* d_out, int out_size) {
    (void)in_sizes; (void)n_in;
    const float* x  = (const float*)d_in[0];
    const float* wr = (const float*)d_in[1];
    const float* br = (const float*)d_in[2];
    const float* w1 = (const float*)d_in[3];
    const float* b1 = (const float*)d_in[4];
    const float* w2 = (const float*)d_in[5];
    const float* b2 = (const float*)d_in[6];
    float* out = (float*)d_out;

    static int smem_set = 0;
    if (!smem_set) {
        cudaFuncSetAttribute(k_gemm, cudaFuncAttributeMaxDynamicSharedMemorySize, SM_TOTAL);
        smem_set = 1;
    }

    // 0) router scores (fp32 exact)
    k_router<<<(B_ * L_ * 32) / 256, 256>>>(x, wr, br);

    // 1) threshold + index build (fused)
    k_topksel<<<B_, 1024>>>();

    // 2) gather -> fp16  +  both weight transposes -> fp16 K-major (one launch)
    k_prep<<<NB_PREP, 256>>>(x, w1, w2);

    // 3) GEMM1 (profiled slot)
    k_gemm<<<dim3(DF_ / 128, BK / 128), 128, SM_TOTAL>>>(b1, out, D_,  DF_, 0);

    // 4) zero output (gemm1 never touches out; completes before gemm2 scatter)
    k_zero<<<2048, 256>>>((float4*)out, (size_t)out_size / 4);

    // 5) GEMM2 (scatter epilogue)
    k_gemm<<<dim3(D_ / 128, BK / 128), 128, SM_TOTAL>>>(b2, out, DF_, D_, 1);
}